// round 5
// baseline (speedup 1.0000x reference)
#include <cuda_runtime.h>
#include <math.h>

#define Bn 8
#define An 100000
#define Cn 80
#define TOPN 1000
#define MAXOBJ 100
#define CAP 32768

__device__ unsigned      g_keys[Bn * An];
__device__ unsigned      g_hist[Bn * 4096];
__device__ unsigned      g_cand[Bn * CAP];
__device__ unsigned      g_ccnt[Bn];
__device__ float4        g_topb[Bn * 1024];
__device__ float         g_tops[Bn * 1024];
__device__ float         g_topc[Bn * 1024];
__device__ float         g_area[Bn * 1024];
__device__ unsigned      g_valid[Bn * 32];
__device__ unsigned      g_mask[Bn * 32000];

// ---------- kernel 0: reset per-replay scratch ----------
__global__ void k_zero() {
    int i = blockIdx.x * 256 + threadIdx.x;
    if (i < Bn * 4096) g_hist[i] = 0u;
    if (i < Bn) g_ccnt[i] = 0u;
}

// ---------- kernel 1: direct-LDG class-max (4 threads/anchor) + hist + cand push ----------
__global__ __launch_bounds__(256) void k_score(const float4* __restrict__ cls4) {
    int T = blockIdx.x * 256 + threadIdx.x;
    int a = T >> 2, r = T & 3;
    if (a >= Bn * An) return;
    const float4* p = cls4 + (size_t)a * 20;
    float m = -1.f;
#pragma unroll
    for (int k = 0; k < 5; ++k) {
        float4 v = __ldg(p + 4 * k + r);
        m = fmaxf(m, fmaxf(fmaxf(v.x, v.y), fmaxf(v.z, v.w)));
    }
    m = fmaxf(m, __shfl_xor_sync(0xffffffffu, m, 1));
    m = fmaxf(m, __shfl_xor_sync(0xffffffffu, m, 2));
    if (r == 0) {
        int b = a / An;
        int al = a - b * An;
        unsigned bits = __float_as_uint(m);
        unsigned u;
        if (m > 0.05f) u = (bits < 0x3F800000u) ? (0x3F800000u - bits) : 0u;
        else           u = 0xFFFFFFFFu;
        g_keys[a] = u;
        if (u < 16380u) {
            atomicAdd(&g_hist[b * 4096 + (u >> 2)], 1u);
            unsigned p2 = atomicAdd(&g_ccnt[b], 1u);
            if (p2 < CAP) g_cand[b * CAP + p2] = (u << 17) | (unsigned)al;
        }
    }
}

// ---------- kernel 2: cut from histogram + candidate compaction + sort + gather ----------
__global__ __launch_bounds__(1024) void k_select(const float* __restrict__ cls,
                                                 const float4* __restrict__ reg,
                                                 const float4* __restrict__ anc) {
    int b = blockIdx.x, tid = threadIdx.x;
    int lane = tid & 31, wid = tid >> 5;
    __shared__ unsigned long long sk[1024];
    __shared__ unsigned wsum[32];
    __shared__ int s_cut;
    __shared__ unsigned s_tot, s_n;

    if (tid == 0) { s_cut = -1; s_tot = 0u; s_n = 0u; }
    __syncthreads();

    // prefix scan over 4096 global hist buckets, find cut (cum >= TOPN)
    uint4 h4 = reinterpret_cast<const uint4*>(g_hist + b * 4096)[tid];
    unsigned h0 = h4.x, h1 = h4.y, h2 = h4.z, h3 = h4.w;
    unsigned s = h0 + h1 + h2 + h3;
    unsigned x = s;
#pragma unroll
    for (int o = 1; o < 32; o <<= 1) {
        unsigned y = __shfl_up_sync(0xffffffffu, x, o);
        if (lane >= o) x += y;
    }
    if (lane == 31) wsum[wid] = x;
    __syncthreads();
    if (tid < 32) {
        unsigned v = wsum[tid];
#pragma unroll
        for (int o = 1; o < 32; o <<= 1) {
            unsigned y = __shfl_up_sync(0xffffffffu, v, o);
            if (tid >= o) v += y;
        }
        wsum[tid] = v;
    }
    __syncthreads();
    unsigned incl = x + (wid ? wsum[wid - 1] : 0u);
    unsigned excl = incl - s;
    if (excl < TOPN && incl >= TOPN) {
        int cut; unsigned c;
        if (excl + h0 >= TOPN)                { cut = 4 * tid;     c = excl + h0; }
        else if (excl + h0 + h1 >= TOPN)      { cut = 4 * tid + 1; c = excl + h0 + h1; }
        else if (excl + h0 + h1 + h2 >= TOPN) { cut = 4 * tid + 2; c = excl + h0 + h1 + h2; }
        else                                  { cut = 4 * tid + 3; c = excl + h0 + h1 + h2 + h3; }
        s_cut = cut; s_tot = c;
    }
    __syncthreads();

    unsigned ccnt = g_ccnt[b];
    bool fast = (s_cut >= 0) && (s_tot <= 1024u) && (ccnt <= CAP);
    if (fast) {
        unsigned ulimit = ((unsigned)s_cut + 1u) << 2;
        const unsigned* cand = g_cand + b * CAP;
        for (unsigned c = tid; c < ccnt; c += 1024) {
            unsigned key = cand[c];
            if ((key >> 17) < ulimit) {
                unsigned p = atomicAdd(&s_n, 1u);
                sk[p] = (unsigned long long)key;
            }
        }
    } else {
        // exact bitwise radix select over full key set (correctness net; cold path)
        const unsigned* keys = g_keys + (size_t)b * An;
        unsigned long long pref = 0ull;
        int rankNeed = TOPN;
        __shared__ unsigned s_c;
        for (int bit = 48; bit >= 0; --bit) {
            if (tid == 0) s_c = 0u;
            __syncthreads();
            unsigned c = 0;
            for (int a = tid; a < An; a += 1024) {
                unsigned long long k = ((unsigned long long)keys[a] << 17) | (unsigned)a;
                if ((k >> (bit + 1)) == pref && !((k >> bit) & 1ull)) c++;
            }
#pragma unroll
            for (int o = 16; o; o >>= 1) c += __shfl_down_sync(0xffffffffu, c, o);
            if (lane == 0) atomicAdd(&s_c, c);
            __syncthreads();
            unsigned C0 = s_c;
            if (rankNeed <= (int)C0) pref <<= 1;
            else { pref = (pref << 1) | 1ull; rankNeed -= (int)C0; }
            __syncthreads();
        }
        for (int a = tid; a < An; a += 1024) {
            unsigned long long k = ((unsigned long long)keys[a] << 17) | (unsigned)a;
            if (k <= pref) {
                unsigned p = atomicAdd(&s_n, 1u);
                if (p < 1024u) sk[p] = k;
            }
        }
    }
    __syncthreads();
    unsigned n = s_n;
    if ((unsigned)tid >= n) sk[tid] = ~0ull;
    __syncthreads();

    // bitonic sort 1024 ascending (smaller key = higher score, then smaller idx)
    for (int kk = 2; kk <= 1024; kk <<= 1) {
        for (int j = kk >> 1; j > 0; j >>= 1) {
            int ixj = tid ^ j;
            if (ixj > tid) {
                unsigned long long a0 = sk[tid], a1 = sk[ixj];
                bool asc = (tid & kk) == 0;
                if (asc ? (a0 > a1) : (a0 < a1)) { sk[tid] = a1; sk[ixj] = a0; }
            }
            __syncthreads();
        }
    }

    float sc = 0.f;
    if (tid < TOPN) {
        unsigned long long k = sk[tid];
        int a = (int)(k & 0x1FFFFull);
        unsigned u = (unsigned)(k >> 17);
        sc = (u >= 0x3F800000u) ? 0.f : __uint_as_float(0x3F800000u - u);

        const float4* c4 = reinterpret_cast<const float4*>(cls + ((size_t)b * An + a) * Cn);
        float best = -1.f; int bc = 0;
#pragma unroll
        for (int q = 0; q < Cn / 4; ++q) {
            float4 v = __ldg(c4 + q);
            if (v.x > best) { best = v.x; bc = 4 * q; }
            if (v.y > best) { best = v.y; bc = 4 * q + 1; }
            if (v.z > best) { best = v.z; bc = 4 * q + 2; }
            if (v.w > best) { best = v.w; bc = 4 * q + 3; }
        }

        float4 rg = __ldg(reg + (size_t)b * An + a);
        float4 an = __ldg(anc + (size_t)b * An + a);
        float aw  = __fsub_rn(an.z, an.x), ah = __fsub_rn(an.w, an.y);
        float acx = __fadd_rn(an.x, __fmul_rn(0.5f, aw));
        float acy = __fadd_rn(an.y, __fmul_rn(0.5f, ah));
        float pw  = __fmul_rn(expf(rg.z), aw);
        float ph  = __fmul_rn(expf(rg.w), ah);
        float pcx = __fadd_rn(__fmul_rn(rg.x, aw), acx);
        float pcy = __fadd_rn(__fmul_rn(rg.y, ah), acy);
        float hw  = __fmul_rn(0.5f, pw), hh = __fmul_rn(0.5f, ph);
        float x1 = truncf(__fsub_rn(pcx, hw));
        float y1 = truncf(__fsub_rn(pcy, hh));
        float x2 = truncf(__fadd_rn(pcx, hw));
        float y2 = truncf(__fadd_rn(pcy, hh));

        g_topb[b * 1024 + tid] = make_float4(x1, y1, x2, y2);
        g_tops[b * 1024 + tid] = sc;
        g_topc[b * 1024 + tid] = (float)bc;
        g_area[b * 1024 + tid] = fmaxf(__fmul_rn(__fsub_rn(x2, x1), __fsub_rn(y2, y1)), 1e-4f);
    } else {
        g_topb[b * 1024 + tid] = make_float4(1e9f, 1e9f, 1e9f, 1e9f);
        g_area[b * 1024 + tid] = 1e9f;
    }
    bool v = (tid < TOPN) && (sc > 0.05f);
    unsigned wm = __ballot_sync(0xffffffffu, v);
    if (lane == 0) g_valid[b * 32 + wid] = wm;
}

// ---------- kernel 3: suppression bitmask; warp = 32 rows, same word ----------
__global__ __launch_bounds__(256) void k_mask() {
    int b = blockIdx.y;
    __shared__ float4 sb[1024];
    __shared__ float  sa[1024];
    for (int t = threadIdx.x; t < 1024; t += 256) {
        sb[t] = g_topb[b * 1024 + t];
        sa[t] = g_area[b * 1024 + t];
    }
    __syncthreads();
    int m = blockIdx.x * 256 + threadIdx.x;
    int w = m >> 10, i = m & 1023;
    if (i >= TOPN) return;
    unsigned bits = 0u;
    int jbase = w << 5;
    if (jbase + 31 > i) {
        float4 bi = sb[i]; float ai = sa[i];
#pragma unroll
        for (int t = 0; t < 32; ++t) {
            int j = jbase + t;
            float4 bj = sb[j]; float aj = sa[j];
            float tlx = fmaxf(bi.x, bj.x), tly = fmaxf(bi.y, bj.y);
            float brx = fminf(bi.z, bj.z), bry = fminf(bi.w, bj.w);
            float sx = fmaxf(__fsub_rn(brx, tlx), 0.f);
            float sy = fmaxf(__fsub_rn(bry, tly), 0.f);
            float inter = __fmul_rn(sx, sy);
            bool sup = (__fadd_rn(inter, inter) >= __fsub_rn(__fadd_rn(ai, aj), inter))
                       && (j > i);
            bits |= sup ? (1u << t) : 0u;
        }
    }
    g_mask[b * 32000 + i * 32 + w] = bits;
}

// ---------- kernel 4: early-exit ffs-greedy NMS + compaction ----------
extern __shared__ unsigned shm[];
__global__ __launch_bounds__(1024) void k_nms(float* __restrict__ out) {
    int b = blockIdx.x, tid = threadIdx.x;
    __shared__ unsigned s_kept[32];
    __shared__ int s_base[32];

    const uint4* src = reinterpret_cast<const uint4*>(g_mask + (size_t)b * 32000);
    uint4* dst = reinterpret_cast<uint4*>(shm);
    for (int i = tid; i < 8000; i += 1024) dst[i] = src[i];
    if (tid < MAXOBJ) {
        out[b * MAXOBJ + tid] = -1.f;
        out[Bn * MAXOBJ + b * MAXOBJ + tid] = -1.f;
    }
    if (tid < MAXOBJ * 4) out[2 * Bn * MAXOBJ + b * MAXOBJ * 4 + tid] = 0.f;
    __syncthreads();

    if (tid < 32) {
        int lane = tid;
        unsigned valid = g_valid[b * 32 + lane];
        unsigned supp = ~valid;
        unsigned done = 0u, kept = 0u;
        int kcount = 0;
        while (true) {
            unsigned rem = ~supp & ~done;
            unsigned bal = __ballot_sync(0xffffffffu, rem != 0u);
            if (!bal) break;
            int wf = __ffs(bal) - 1;
            unsigned remw = __shfl_sync(0xffffffffu, rem, wf);
            int t = __ffs(remw) - 1;
            int i = wf * 32 + t;
            if (lane == wf) { kept |= (1u << t); done |= (1u << t); }
            kcount++;
            if (kcount >= MAXOBJ) break;    // output full: later kept boxes irrelevant
            supp |= shm[i * 32 + lane];
        }
        s_kept[lane] = kept;
        int c = __popc(kept), x = c;
#pragma unroll
        for (int o = 1; o < 32; o <<= 1) {
            int y = __shfl_up_sync(0xffffffffu, x, o);
            if (lane >= o) x += y;
        }
        s_base[lane] = x - c;
    }
    __syncthreads();

    if (tid < TOPN) {
        int w = tid >> 5, bt = tid & 31;
        unsigned kw = s_kept[w];
        if ((kw >> bt) & 1u) {
            int r = s_base[w] + __popc(kw & ((1u << bt) - 1u));
            if (r < MAXOBJ) {
                out[b * MAXOBJ + r] = g_tops[b * 1024 + tid];
                out[Bn * MAXOBJ + b * MAXOBJ + r] = g_topc[b * 1024 + tid];
                float4 bx = g_topb[b * 1024 + tid];
                float* ob = out + 2 * Bn * MAXOBJ + (b * MAXOBJ + r) * 4;
                ob[0] = bx.x; ob[1] = bx.y; ob[2] = bx.z; ob[3] = bx.w;
            }
        }
    }
}

extern "C" void kernel_launch(void* const* d_in, const int* in_sizes, int n_in,
                              void* d_out, int out_size) {
    const float*  cls = (const float*)d_in[0];
    const float4* reg = (const float4*)d_in[1];
    const float4* anc = (const float4*)d_in[2];
    float* out = (float*)d_out;

    cudaFuncSetAttribute(k_nms, cudaFuncAttributeMaxDynamicSharedMemorySize, 128000);

    k_zero<<<128, 256>>>();
    k_score<<<(Bn * An * 4 + 255) / 256, 256>>>((const float4*)cls);
    k_select<<<Bn, 1024>>>(cls, reg, anc);
    k_mask<<<dim3(128, Bn), 256>>>();
    k_nms<<<Bn, 1024, 128000>>>(out);
}

// round 6
// speedup vs baseline: 1.0556x; 1.0556x over previous
#include <cuda_runtime.h>
#include <math.h>

#define Bn 8
#define An 100000
#define Cn 80
#define TOPN 1000
#define MAXOBJ 100
#define CAP 32768

__device__ unsigned      g_keys[Bn * An];
__device__ unsigned      g_cand[Bn * CAP];
__device__ unsigned      g_ccnt[Bn];          // zero-init; reset by k_nms tail each call
__device__ float4        g_topb[Bn * 1024];
__device__ float         g_tops[Bn * 1024];
__device__ float         g_topc[Bn * 1024];
__device__ float         g_area[Bn * 1024];
__device__ unsigned      g_valid[Bn * 32];
__device__ unsigned      g_mask[Bn * 32000];

// ---------- kernel 1: direct-LDG class-max (4 threads/anchor) + candidate push ----------
__global__ __launch_bounds__(256) void k_score(const float4* __restrict__ cls4) {
    int T = blockIdx.x * 256 + threadIdx.x;
    int a = T >> 2, r = T & 3;
    if (a >= Bn * An) return;
    const float4* p = cls4 + (size_t)a * 20;
    float m = -1.f;
#pragma unroll
    for (int k = 0; k < 5; ++k) {
        float4 v = __ldg(p + 4 * k + r);
        m = fmaxf(m, fmaxf(fmaxf(v.x, v.y), fmaxf(v.z, v.w)));
    }
    m = fmaxf(m, __shfl_xor_sync(0xffffffffu, m, 1));
    m = fmaxf(m, __shfl_xor_sync(0xffffffffu, m, 2));
    if (r == 0) {
        int b = a / An;
        int al = a - b * An;
        unsigned bits = __float_as_uint(m);
        unsigned u;
        if (m > 0.05f) u = (bits < 0x3F800000u) ? (0x3F800000u - bits) : 0u;
        else           u = 0xFFFFFFFFu;
        g_keys[a] = u;
        if (u < 16380u) {
            unsigned p2 = atomicAdd(&g_ccnt[b], 1u);
            if (p2 < CAP) g_cand[b * CAP + p2] = (u << 17) | (unsigned)al;
        }
    }
}

// ---------- kernel 2: smem hist from candidates + cut + compact + sort + gather ----------
__global__ __launch_bounds__(1024) void k_select(const float* __restrict__ cls,
                                                 const float4* __restrict__ reg,
                                                 const float4* __restrict__ anc) {
    int b = blockIdx.x, tid = threadIdx.x;
    int lane = tid & 31, wid = tid >> 5;
    __shared__ unsigned hist[4096];
    __shared__ unsigned long long sk[1024];
    __shared__ unsigned wsum[32];
    __shared__ int s_cut;
    __shared__ unsigned s_tot, s_n;

    unsigned ccnt = g_ccnt[b];
    unsigned cc = (ccnt < (unsigned)CAP) ? ccnt : (unsigned)CAP;
    const unsigned* cand = g_cand + b * CAP;

    for (int i = tid; i < 4096; i += 1024) hist[i] = 0u;
    if (tid == 0) { s_cut = -1; s_tot = 0u; s_n = 0u; }
    __syncthreads();

    for (unsigned c = tid; c < cc; c += 1024)
        atomicAdd(&hist[(cand[c] >> 17) >> 2], 1u);
    __syncthreads();

    // prefix scan over 4096 buckets (4 per thread), find cut (cum >= TOPN)
    unsigned h0 = hist[4 * tid], h1 = hist[4 * tid + 1],
             h2 = hist[4 * tid + 2], h3 = hist[4 * tid + 3];
    unsigned s = h0 + h1 + h2 + h3;
    unsigned x = s;
#pragma unroll
    for (int o = 1; o < 32; o <<= 1) {
        unsigned y = __shfl_up_sync(0xffffffffu, x, o);
        if (lane >= o) x += y;
    }
    if (lane == 31) wsum[wid] = x;
    __syncthreads();
    if (tid < 32) {
        unsigned v = wsum[tid];
#pragma unroll
        for (int o = 1; o < 32; o <<= 1) {
            unsigned y = __shfl_up_sync(0xffffffffu, v, o);
            if (tid >= o) v += y;
        }
        wsum[tid] = v;
    }
    __syncthreads();
    unsigned incl = x + (wid ? wsum[wid - 1] : 0u);
    unsigned excl = incl - s;
    if (excl < TOPN && incl >= TOPN) {
        int cut; unsigned c;
        if (excl + h0 >= TOPN)                { cut = 4 * tid;     c = excl + h0; }
        else if (excl + h0 + h1 >= TOPN)      { cut = 4 * tid + 1; c = excl + h0 + h1; }
        else if (excl + h0 + h1 + h2 >= TOPN) { cut = 4 * tid + 2; c = excl + h0 + h1 + h2; }
        else                                  { cut = 4 * tid + 3; c = excl + h0 + h1 + h2 + h3; }
        s_cut = cut; s_tot = c;
    }
    __syncthreads();

    bool fast = (s_cut >= 0) && (s_tot <= 1024u) && (ccnt <= (unsigned)CAP);
    if (fast) {
        unsigned ulimit = ((unsigned)s_cut + 1u) << 2;
        for (unsigned c = tid; c < cc; c += 1024) {
            unsigned key = cand[c];
            if ((key >> 17) < ulimit) {
                unsigned p = atomicAdd(&s_n, 1u);
                sk[p] = (unsigned long long)key;
            }
        }
    } else {
        // exact bitwise radix select over full key set (cold correctness net)
        const unsigned* keys = g_keys + (size_t)b * An;
        unsigned long long pref = 0ull;
        int rankNeed = TOPN;
        __shared__ unsigned s_c;
        for (int bit = 48; bit >= 0; --bit) {
            if (tid == 0) s_c = 0u;
            __syncthreads();
            unsigned c = 0;
            for (int a = tid; a < An; a += 1024) {
                unsigned long long k = ((unsigned long long)keys[a] << 17) | (unsigned)a;
                if ((k >> (bit + 1)) == pref && !((k >> bit) & 1ull)) c++;
            }
#pragma unroll
            for (int o = 16; o; o >>= 1) c += __shfl_down_sync(0xffffffffu, c, o);
            if (lane == 0) atomicAdd(&s_c, c);
            __syncthreads();
            unsigned C0 = s_c;
            if (rankNeed <= (int)C0) pref <<= 1;
            else { pref = (pref << 1) | 1ull; rankNeed -= (int)C0; }
            __syncthreads();
        }
        for (int a = tid; a < An; a += 1024) {
            unsigned long long k = ((unsigned long long)keys[a] << 17) | (unsigned)a;
            if (k <= pref) {
                unsigned p = atomicAdd(&s_n, 1u);
                if (p < 1024u) sk[p] = k;
            }
        }
    }
    __syncthreads();
    unsigned n = s_n;
    if ((unsigned)tid >= n) sk[tid] = ~0ull;
    __syncthreads();

    // bitonic sort 1024 ascending (smaller key = higher score, then smaller idx)
    for (int kk = 2; kk <= 1024; kk <<= 1) {
        for (int j = kk >> 1; j > 0; j >>= 1) {
            int ixj = tid ^ j;
            if (ixj > tid) {
                unsigned long long a0 = sk[tid], a1 = sk[ixj];
                bool asc = (tid & kk) == 0;
                if (asc ? (a0 > a1) : (a0 < a1)) { sk[tid] = a1; sk[ixj] = a0; }
            }
            __syncthreads();
        }
    }

    float sc = 0.f;
    if (tid < TOPN) {
        unsigned long long k = sk[tid];
        int a = (int)(k & 0x1FFFFull);
        unsigned u = (unsigned)(k >> 17);
        sc = (u >= 0x3F800000u) ? 0.f : __uint_as_float(0x3F800000u - u);

        const float4* c4 = reinterpret_cast<const float4*>(cls + ((size_t)b * An + a) * Cn);
        float best = -1.f; int bc = 0;
#pragma unroll
        for (int q = 0; q < Cn / 4; ++q) {
            float4 v = __ldg(c4 + q);
            if (v.x > best) { best = v.x; bc = 4 * q; }
            if (v.y > best) { best = v.y; bc = 4 * q + 1; }
            if (v.z > best) { best = v.z; bc = 4 * q + 2; }
            if (v.w > best) { best = v.w; bc = 4 * q + 3; }
        }

        float4 rg = __ldg(reg + (size_t)b * An + a);
        float4 an = __ldg(anc + (size_t)b * An + a);
        float aw  = __fsub_rn(an.z, an.x), ah = __fsub_rn(an.w, an.y);
        float acx = __fadd_rn(an.x, __fmul_rn(0.5f, aw));
        float acy = __fadd_rn(an.y, __fmul_rn(0.5f, ah));
        float pw  = __fmul_rn(expf(rg.z), aw);
        float ph  = __fmul_rn(expf(rg.w), ah);
        float pcx = __fadd_rn(__fmul_rn(rg.x, aw), acx);
        float pcy = __fadd_rn(__fmul_rn(rg.y, ah), acy);
        float hw  = __fmul_rn(0.5f, pw), hh = __fmul_rn(0.5f, ph);
        float x1 = truncf(__fsub_rn(pcx, hw));
        float y1 = truncf(__fsub_rn(pcy, hh));
        float x2 = truncf(__fadd_rn(pcx, hw));
        float y2 = truncf(__fadd_rn(pcy, hh));

        g_topb[b * 1024 + tid] = make_float4(x1, y1, x2, y2);
        g_tops[b * 1024 + tid] = sc;
        g_topc[b * 1024 + tid] = (float)bc;
        g_area[b * 1024 + tid] = fmaxf(__fmul_rn(__fsub_rn(x2, x1), __fsub_rn(y2, y1)), 1e-4f);
    } else {
        g_topb[b * 1024 + tid] = make_float4(1e9f, 1e9f, 1e9f, 1e9f);
        g_area[b * 1024 + tid] = 1e9f;
    }
    bool v = (tid < TOPN) && (sc > 0.05f);
    unsigned wm = __ballot_sync(0xffffffffu, v);
    if (lane == 0) g_valid[b * 32 + wid] = wm;
}

// ---------- kernel 3: suppression bitmask v2 (tiny staging, triangle skip) ----------
__global__ __launch_bounds__(256) void k_mask() {
    int b = blockIdx.y;
    int bx = blockIdx.x;              // 0..127
    int w = bx >> 2;                  // word 0..31
    int ibase = (bx & 3) << 8;        // row base 0/256/512/768
    int jbase = w << 5;
    if (jbase + 31 <= ibase) return;  // entire block is lower-triangle: never read

    __shared__ float4 sbj[32];
    __shared__ float  saj[32];
    if (threadIdx.x < 32) {
        sbj[threadIdx.x] = g_topb[b * 1024 + jbase + threadIdx.x];
        saj[threadIdx.x] = g_area[b * 1024 + jbase + threadIdx.x];
    }
    __syncthreads();

    int i = ibase + threadIdx.x;
    if (i >= TOPN) return;
    if (jbase + 31 <= i) return;      // this row's word is lower-triangle: never read

    float4 bi = g_topb[b * 1024 + i];
    float  ai = g_area[b * 1024 + i];
    unsigned bits = 0u;
#pragma unroll
    for (int t = 0; t < 32; ++t) {
        float4 bj = sbj[t]; float aj = saj[t];
        float tlx = fmaxf(bi.x, bj.x), tly = fmaxf(bi.y, bj.y);
        float brx = fminf(bi.z, bj.z), bry = fminf(bi.w, bj.w);
        float sx = fmaxf(__fsub_rn(brx, tlx), 0.f);
        float sy = fmaxf(__fsub_rn(bry, tly), 0.f);
        float inter = __fmul_rn(sx, sy);
        // exact: inter/union >= 0.5  <=>  3*inter >= ai+aj (integer-valued f32)
        bits |= (__fmul_rn(3.f, inter) >= __fadd_rn(ai, aj)) ? (1u << t) : 0u;
    }
    if (jbase <= i) bits &= ~((2u << (i - jbase)) - 1u);   // drop j <= i in diagonal word
    g_mask[b * 32000 + i * 32 + w] = bits;
}

// ---------- kernel 4: early-exit ffs-greedy NMS + compaction + state reset ----------
extern __shared__ unsigned shm[];
__global__ __launch_bounds__(1024) void k_nms(float* __restrict__ out) {
    int b = blockIdx.x, tid = threadIdx.x;
    __shared__ unsigned s_kept[32];
    __shared__ int s_base[32];

    const uint4* src = reinterpret_cast<const uint4*>(g_mask + (size_t)b * 32000);
    uint4* dst = reinterpret_cast<uint4*>(shm);
    for (int i = tid; i < 8000; i += 1024) dst[i] = src[i];
    if (tid < MAXOBJ) {
        out[b * MAXOBJ + tid] = -1.f;
        out[Bn * MAXOBJ + b * MAXOBJ + tid] = -1.f;
    }
    if (tid < MAXOBJ * 4) out[2 * Bn * MAXOBJ + b * MAXOBJ * 4 + tid] = 0.f;
    if (tid == 0) g_ccnt[b] = 0u;          // reset for next graph replay
    __syncthreads();

    if (tid < 32) {
        int lane = tid;
        unsigned valid = g_valid[b * 32 + lane];
        unsigned supp = ~valid;
        unsigned done = 0u, kept = 0u;
        int kcount = 0;
        while (true) {
            unsigned rem = ~supp & ~done;
            unsigned bal = __ballot_sync(0xffffffffu, rem != 0u);
            if (!bal) break;
            int wf = __ffs(bal) - 1;
            unsigned remw = __shfl_sync(0xffffffffu, rem, wf);
            int t = __ffs(remw) - 1;
            int i = wf * 32 + t;
            if (lane == wf) { kept |= (1u << t); done |= (1u << t); }
            kcount++;
            if (kcount >= MAXOBJ) break;   // output full: later kept boxes irrelevant
            unsigned rw = shm[i * 32 + lane];
            supp |= (lane >= (i >> 5)) ? rw : 0u;   // lower-tri words are unwritten garbage
        }
        s_kept[lane] = kept;
        int c = __popc(kept), x = c;
#pragma unroll
        for (int o = 1; o < 32; o <<= 1) {
            int y = __shfl_up_sync(0xffffffffu, x, o);
            if (lane >= o) x += y;
        }
        s_base[lane] = x - c;
    }
    __syncthreads();

    if (tid < TOPN) {
        int w = tid >> 5, bt = tid & 31;
        unsigned kw = s_kept[w];
        if ((kw >> bt) & 1u) {
            int r = s_base[w] + __popc(kw & ((1u << bt) - 1u));
            if (r < MAXOBJ) {
                out[b * MAXOBJ + r] = g_tops[b * 1024 + tid];
                out[Bn * MAXOBJ + b * MAXOBJ + r] = g_topc[b * 1024 + tid];
                float4 bx = g_topb[b * 1024 + tid];
                float* ob = out + 2 * Bn * MAXOBJ + (b * MAXOBJ + r) * 4;
                ob[0] = bx.x; ob[1] = bx.y; ob[2] = bx.z; ob[3] = bx.w;
            }
        }
    }
}

extern "C" void kernel_launch(void* const* d_in, const int* in_sizes, int n_in,
                              void* d_out, int out_size) {
    const float*  cls = (const float*)d_in[0];
    const float4* reg = (const float4*)d_in[1];
    const float4* anc = (const float4*)d_in[2];
    float* out = (float*)d_out;

    cudaFuncSetAttribute(k_nms, cudaFuncAttributeMaxDynamicSharedMemorySize, 128000);

    k_score<<<(Bn * An * 4 + 255) / 256, 256>>>((const float4*)cls);
    k_select<<<Bn, 1024>>>(cls, reg, anc);
    k_mask<<<dim3(128, Bn), 256>>>();
    k_nms<<<Bn, 1024, 128000>>>(out);
}